// round 1
// baseline (speedup 1.0000x reference)
#include <cuda_runtime.h>

// Problem constants
#define BN   8
#define CN   256
#define HN   64
#define WN   64
#define GN   4
#define KKN  9
#define CG   64          // channels per group
#define OCF  108         // offset-branch output channels = 3*G*K*K
#define HWN  (HN*WN)

// Scratch (device globals; no runtime allocation allowed)
__device__ float g_off[BN*OCF*HWN];          // offset/mask conv output
__device__ float g_out[BN*CN*HWN];           // DCN conv output (pre-LN)
__device__ float g_wT [GN*KKN*CG*CG];        // w_dcn transposed to [g][k][c][oc]

// ---------------------------------------------------------------------------
// Kernel 0: transpose w_dcn [256][64][3][3] -> g_wT[g][k][c][oc]
// ---------------------------------------------------------------------------
__global__ void __launch_bounds__(256) transpose_wdcn_k(const float* __restrict__ w_dcn)
{
    int i = blockIdx.x * 256 + threadIdx.x;
    if (i < GN*KKN*CG*CG) {
        int oc = i & 63;
        int c  = (i >> 6) & 63;
        int gk = i >> 12;          // g*9 + k
        int k  = gk % 9;
        int g  = gk / 9;
        g_wT[i] = w_dcn[((g*CG + oc)*CG + c)*KKN + k];
    }
}

// ---------------------------------------------------------------------------
// Kernel 1: offset/mask conv  (C=256 -> 108, 3x3, SAME, +bias)
// grid (HN/2, BN), block 256.  Block computes 2 rows x 64 cols x 108 oc.
// Thread tile: 8 px x 7 oc.
// ---------------------------------------------------------------------------
__global__ void __launch_bounds__(256) offset_conv_k(
    const float* __restrict__ x, const float* __restrict__ w_off,
    const float* __restrict__ b_off)
{
    __shared__ float xs[8][4][66];    // 8 in-ch chunk, 4 rows (h0-1..h0+2), 66 cols
    __shared__ float ws[112][72];     // [oc(padded)][c*9+k]

    const int h0   = blockIdx.x * 2;
    const int b    = blockIdx.y;
    const int t    = threadIdx.x;
    const int pxg  = t & 15;          // 16 pixel groups of 8
    const int ocg  = t >> 4;          // 16 oc groups of 7
    const int px0  = pxg * 8;
    const int prow = px0 >> 6;        // 0 or 1
    const int pcol0 = px0 & 63;

    float acc[7][8];
#pragma unroll
    for (int j = 0; j < 7; j++)
#pragma unroll
        for (int i = 0; i < 8; i++) acc[j][i] = 0.f;

    for (int cb = 0; cb < CN; cb += 8) {
        __syncthreads();
        // Load x patch: 8 channels x 4 rows x 66 cols (zero-padded borders)
        for (int i = t; i < 8*4*66; i += 256) {
            int c   = i / 264;
            int rem = i - c*264;
            int r   = rem / 66;
            int col = rem - r*66;
            int y   = h0 - 1 + r;
            int xx  = col - 1;
            float v = 0.f;
            if (y >= 0 && y < HN && xx >= 0 && xx < WN)
                v = x[((b*CN + cb + c)*HN + y)*WN + xx];
            xs[c][r][col] = v;
        }
        // Load weight panel: 108 oc x (8c x 9k)
        for (int i = t; i < OCF*72; i += 256) {
            int oc  = i / 72;
            int rem = i - oc*72;
            int c   = rem / 9;
            int k   = rem - c*9;
            ws[oc][rem] = w_off[(oc*CN + cb + c)*KKN + k];
        }
        // zero padded oc rows 108..111
        for (int i = t; i < 4*72; i += 256) ws[108 + i/72][i - (i/72)*72] = 0.f;
        __syncthreads();

#pragma unroll
        for (int c = 0; c < 8; c++) {
#pragma unroll
            for (int ky = 0; ky < 3; ky++) {
#pragma unroll
                for (int kx = 0; kx < 3; kx++) {
                    float xv[8];
#pragma unroll
                    for (int i = 0; i < 8; i++)
                        xv[i] = xs[c][prow + ky][pcol0 + kx + i];
                    const int kk = ky*3 + kx;
#pragma unroll
                    for (int j = 0; j < 7; j++) {
                        float wv = ws[ocg*7 + j][c*9 + kk];
#pragma unroll
                        for (int i = 0; i < 8; i++)
                            acc[j][i] = fmaf(wv, xv[i], acc[j][i]);
                    }
                }
            }
        }
    }

    const int h = h0 + prow;
#pragma unroll
    for (int j = 0; j < 7; j++) {
        int oc = ocg*7 + j;
        if (oc < OCF) {
            float bo = b_off[oc];
#pragma unroll
            for (int i = 0; i < 8; i++)
                g_off[((b*OCF + oc)*HN + h)*WN + pcol0 + i] = acc[j][i] + bo;
        }
    }
}

// ---------------------------------------------------------------------------
// Kernel 2: deformable sampling + grouped conv
// grid (HN/2, GN, BN), block 256, dynamic smem.
// Block computes 128 px (2 rows) x 64 oc for one (b,g), looping k=0..8.
// ---------------------------------------------------------------------------
#define SPITCH     132
#define SM2_S      4096                        // Wsm: [64c][64oc]
#define SM2_WWT    (SM2_S + CG*SPITCH)         // S:   [64c][SPITCH]
#define SM2_WIDX   (SM2_WWT + 4*128)           // wwt: [4][128]
#define SM2_FLOATS (SM2_WIDX + 4*128)          // widx (int): [4][128]

__global__ void __launch_bounds__(256) dcn_k(
    const float* __restrict__ x, const float* __restrict__ b_dcn)
{
    extern __shared__ float sm[];
    float* Wsm  = sm;
    float* S    = sm + SM2_S;
    float* wwt  = sm + SM2_WWT;
    int*   widx = (int*)(sm + SM2_WIDX);

    const int h0 = blockIdx.x * 2;
    const int g  = blockIdx.y;
    const int b  = blockIdx.z;
    const int t  = threadIdx.x;
    const int px0 = (t & 15) * 8;      // 16 px groups of 8
    const int oc0 = (t >> 4) * 4;      // 16 oc groups of 4

    float acc[4][8];
#pragma unroll
    for (int j = 0; j < 4; j++)
#pragma unroll
        for (int i = 0; i < 8; i++) acc[j][i] = 0.f;

    const int pB     = t & 127;        // pixel for Phase B
    const int cstart = t >> 7;         // 0 or 1 (channel parity for Phase B)
    const float* xb  = x + (b*CN + g*CG)*HWN;

    for (int k = 0; k < KKN; k++) {
        // ---- Phase A: per-pixel bilinear corner data (threads 0..127) ----
        if (t < 128) {
            int p  = t;
            int h  = h0 + (p >> 6);
            int w  = p & 63;
            int ky = k / 3 - 1;
            int kx = k - (k/3)*3 - 1;
            int sp = h*WN + w;
            float oy = g_off[b*OCF*HWN + ((g*KKN + k)*2    )*HWN + sp];
            float ox = g_off[b*OCF*HWN + ((g*KKN + k)*2 + 1)*HWN + sp];
            float mz = g_off[b*OCF*HWN + (2*GN*KKN + g*KKN + k)*HWN + sp];
            float mk = 1.f / (1.f + expf(-mz));
            float py  = (float)(h + ky) + oy;
            float pxx = (float)(w + kx) + ox;
            float y0f = floorf(py),  x0f = floorf(pxx);
            float wy1 = py - y0f,    wx1 = pxx - x0f;
            float wy0 = 1.f - wy1,   wx0 = 1.f - wx1;
            int y0 = (int)y0f, x0i = (int)x0f;
            int y1 = y0 + 1,   x1i = x0i + 1;
            bool vy0 = (y0 >= 0) & (y0 < HN);
            bool vy1 = (y1 >= 0) & (y1 < HN);
            bool vx0 = (x0i >= 0) & (x0i < WN);
            bool vx1 = (x1i >= 0) & (x1i < WN);
            int y0c = min(max(y0, 0), HN-1), y1c = min(max(y1, 0), HN-1);
            int x0c = min(max(x0i,0), WN-1), x1c = min(max(x1i,0), WN-1);
            widx[0*128+p] = y0c*WN + x0c;
            widx[1*128+p] = y0c*WN + x1c;
            widx[2*128+p] = y1c*WN + x0c;
            widx[3*128+p] = y1c*WN + x1c;
            wwt [0*128+p] = (vy0 && vx0) ? wy0*wx0*mk : 0.f;
            wwt [1*128+p] = (vy0 && vx1) ? wy0*wx1*mk : 0.f;
            wwt [2*128+p] = (vy1 && vx0) ? wy1*wx0*mk : 0.f;
            wwt [3*128+p] = (vy1 && vx1) ? wy1*wx1*mk : 0.f;
        }
        // ---- Phase A2: stage weight panel [c][oc] (coalesced from g_wT) ----
        {
            const float* wt = g_wT + (g*KKN + k)*CG*CG;
            for (int i = t; i < CG*CG; i += 256) Wsm[i] = wt[i];
        }
        __syncthreads();

        // ---- Phase B: gather sampled values S[c][p] ----
        {
            float w0 = wwt[0*128+pB], w1 = wwt[1*128+pB];
            float w2 = wwt[2*128+pB], w3 = wwt[3*128+pB];
            int   i0 = widx[0*128+pB], i1 = widx[1*128+pB];
            int   i2 = widx[2*128+pB], i3 = widx[3*128+pB];
#pragma unroll 4
            for (int c = cstart; c < CG; c += 2) {
                const float* xp = xb + c*HWN;
                S[c*SPITCH + pB] = w0*xp[i0] + w1*xp[i1] + w2*xp[i2] + w3*xp[i3];
            }
        }
        __syncthreads();

        // ---- Phase C: smem GEMM  acc[oc][px] += W[c][oc] * S[c][px] ----
#pragma unroll 8
        for (int c = 0; c < CG; c++) {
            float4 w4 = *reinterpret_cast<const float4*>(&Wsm[c*CG + oc0]);
            float4 sA = *reinterpret_cast<const float4*>(&S[c*SPITCH + px0]);
            float4 sB = *reinterpret_cast<const float4*>(&S[c*SPITCH + px0 + 4]);
            float wv[4] = {w4.x, w4.y, w4.z, w4.w};
            float sv[8] = {sA.x, sA.y, sA.z, sA.w, sB.x, sB.y, sB.z, sB.w};
#pragma unroll
            for (int j = 0; j < 4; j++)
#pragma unroll
                for (int i = 0; i < 8; i++)
                    acc[j][i] = fmaf(wv[j], sv[i], acc[j][i]);
        }
        __syncthreads();
    }

    // ---- epilogue: +bias, store ----
    const int h   = h0 + (px0 >> 6);
    const int w0c = px0 & 63;
#pragma unroll
    for (int j = 0; j < 4; j++) {
        int ocgl = g*CG + oc0 + j;
        float bd = b_dcn[ocgl];
        float* op = g_out + ((b*CN + ocgl)*HN + h)*WN + w0c;
#pragma unroll
        for (int i = 0; i < 8; i++) op[i] = acc[j][i] + bd;
    }
}

// ---------------------------------------------------------------------------
// Kernel 3: LayerNorm over C + sigmoid + gate  (out = x * sigmoid(LN(dcn)))
// grid (HN*2, BN), block 256; each block: one h row, 32-px half, all 256 ch.
// ---------------------------------------------------------------------------
__global__ void __launch_bounds__(256) ln_gate_k(
    const float* __restrict__ x, const float* __restrict__ gamma,
    const float* __restrict__ beta, float* __restrict__ out)
{
    __shared__ float tile[CN][32];
    __shared__ float rs[8][32];
    __shared__ float rq[8][32];
    __shared__ float smu[32], srinv[32];

    const int b    = blockIdx.y;
    const int h    = blockIdx.x >> 1;
    const int wseg = (blockIdx.x & 1) * 32;
    const int t    = threadIdx.x;
    const int base = b*CN*HWN + h*WN + wseg;

    for (int i = t; i < CN*32; i += 256) {
        int c = i >> 5, p = i & 31;
        tile[c][p] = g_out[base + c*HWN + p];
    }
    __syncthreads();
    {
        int p = t & 31, part = t >> 5;
        float s = 0.f, q = 0.f;
        for (int c = part; c < CN; c += 8) {
            float v = tile[c][p];
            s += v; q += v*v;
        }
        rs[part][p] = s; rq[part][p] = q;
    }
    __syncthreads();
    if (t < 32) {
        float s = 0.f, q = 0.f;
#pragma unroll
        for (int part = 0; part < 8; part++) { s += rs[part][t]; q += rq[part][t]; }
        float mu  = s * (1.f/CN);
        float var = fmaxf(q * (1.f/CN) - mu*mu, 0.f);
        smu[t]   = mu;
        srinv[t] = rsqrtf(var + 1e-5f);
    }
    __syncthreads();
    for (int i = t; i < CN*32; i += 256) {
        int c = i >> 5, p = i & 31;
        float z = (tile[c][p] - smu[p]) * srinv[p] * gamma[c] + beta[c];
        float a = 1.f / (1.f + expf(-z));
        int idx = base + c*HWN + p;
        out[idx] = x[idx] * a;
    }
}

// ---------------------------------------------------------------------------
// Entry point
// ---------------------------------------------------------------------------
extern "C" void kernel_launch(void* const* d_in, const int* in_sizes, int n_in,
                              void* d_out, int out_size)
{
    const float* x     = (const float*)d_in[0];
    const float* w_off = (const float*)d_in[1];
    const float* b_off = (const float*)d_in[2];
    const float* w_dcn = (const float*)d_in[3];
    const float* b_dcn = (const float*)d_in[4];
    const float* gamma = (const float*)d_in[5];
    const float* beta  = (const float*)d_in[6];
    float* out = (float*)d_out;

    (void)in_sizes; (void)n_in; (void)out_size;

    cudaFuncSetAttribute(dcn_k, cudaFuncAttributeMaxDynamicSharedMemorySize,
                         SM2_FLOATS * (int)sizeof(float));

    transpose_wdcn_k<<<(GN*KKN*CG*CG + 255)/256, 256>>>(w_dcn);
    offset_conv_k<<<dim3(HN/2, BN), 256>>>(x, w_off, b_off);
    dcn_k<<<dim3(HN/2, GN, BN), 256, SM2_FLOATS * sizeof(float)>>>(x, b_dcn);
    ln_gate_k<<<dim3(HN*2, BN), 256>>>(x, gamma, beta, out);
}